// round 1
// baseline (speedup 1.0000x reference)
#include <cuda_runtime.h>
#include <cstdint>
#include <cstddef>

// Problem constants
#define BB 8
#define SS 4096
#define DD 256
#define CC 64            // chunk length
#define NCHUNK 64        // SS / CC

// Scratch: per-(batch,chunk) DxD state contributions; converted in-place to
// per-chunk incoming states by the scan kernel. 8*64*256*256 floats = 134 MB.
__device__ float g_S[(size_t)BB * NCHUNK * DD * DD];
__device__ float g_Lg[BB * NCHUNK * CC];   // in-chunk inclusive cumsum of log(beta)
__device__ float g_Gamma[BB * NCHUNK];     // per-chunk total decay

// ---------------------------------------------------------------------------
// Kernel A: per-chunk decayed state contribution
//   S_c[i][j] = sum_tau exp(Lg[C-1]-Lg[tau]) * k[tau][i] * v[tau][j]
// One CTA per (b,c,quadrant): quadrant = 128x128 block of the 256x256 output.
// 256 threads, 8x8 register tile each.
// ---------------------------------------------------------------------------
__global__ __launch_bounds__(256) void dr_state_kernel(
    const float* __restrict__ K,
    const float* __restrict__ V,
    const float* __restrict__ beta)
{
    const int bc = blockIdx.x;            // b*NCHUNK + c
    const int b  = bc >> 6;
    const int c  = bc & 63;
    const int quad = blockIdx.y;          // 0..3
    const int qi = quad >> 1, qj = quad & 1;
    const int tid = threadIdx.x;

    __shared__ float Kp[32][132];
    __shared__ float Vp[32][132];
    __shared__ float w[CC];
    __shared__ float sLg[CC];

    if (tid < CC) {
        float bt = fmaxf(beta[b * SS + c * CC + tid], 1e-30f);
        sLg[tid] = __logf(bt);
    }
    __syncthreads();
    if (tid == 0) {
        float s = 0.f;
        #pragma unroll
        for (int u = 0; u < CC; u++) { s += sLg[u]; sLg[u] = s; }
    }
    __syncthreads();
    const float LgEnd = sLg[CC - 1];
    if (tid < CC) {
        w[tid] = __expf(LgEnd - sLg[tid]);
        if (quad == 0) g_Lg[bc * CC + tid] = sLg[tid];
    }
    if (quad == 0 && tid == 0) g_Gamma[bc] = __expf(LgEnd);

    float acc[8][8];
    #pragma unroll
    for (int r = 0; r < 8; r++)
        #pragma unroll
        for (int c2 = 0; c2 < 8; c2++) acc[r][c2] = 0.f;

    const int rt = tid >> 4;   // 0..15
    const int ct = tid & 15;   // 0..15
    const int i0 = rt * 8, j0 = ct * 8;

    for (int p = 0; p < 2; p++) {
        __syncthreads();   // also publishes w/sLg on first iteration
        #pragma unroll
        for (int it = 0; it < 4; it++) {
            int idx = it * 1024 + tid * 4;       // 0..4095
            int tau = idx >> 7, x = idx & 127;
            const size_t row = ((size_t)b * SS + (size_t)c * CC + p * 32 + tau) * DD;
            *(float4*)&Kp[tau][x] = *(const float4*)&K[row + qi * 128 + x];
            *(float4*)&Vp[tau][x] = *(const float4*)&V[row + qj * 128 + x];
        }
        __syncthreads();
        #pragma unroll 4
        for (int tau = 0; tau < 32; tau++) {
            const float wt = w[p * 32 + tau];
            float4 ka = *(float4*)&Kp[tau][i0];
            float4 kb = *(float4*)&Kp[tau][i0 + 4];
            float4 va = *(float4*)&Vp[tau][j0];
            float4 vb = *(float4*)&Vp[tau][j0 + 4];
            float kw[8] = { ka.x * wt, ka.y * wt, ka.z * wt, ka.w * wt,
                            kb.x * wt, kb.y * wt, kb.z * wt, kb.w * wt };
            float vv[8] = { va.x, va.y, va.z, va.w, vb.x, vb.y, vb.z, vb.w };
            #pragma unroll
            for (int r = 0; r < 8; r++)
                #pragma unroll
                for (int c2 = 0; c2 < 8; c2++)
                    acc[r][c2] += kw[r] * vv[c2];
        }
    }

    float* Sdst = g_S + (size_t)bc * DD * DD;
    #pragma unroll
    for (int r = 0; r < 8; r++) {
        const int gi = qi * 128 + i0 + r;
        const int gj = qj * 128 + j0;
        float4 s0 = { acc[r][0], acc[r][1], acc[r][2], acc[r][3] };
        float4 s1 = { acc[r][4], acc[r][5], acc[r][6], acc[r][7] };
        *(float4*)&Sdst[(size_t)gi * DD + gj]     = s0;
        *(float4*)&Sdst[(size_t)gi * DD + gj + 4] = s1;
    }
}

// ---------------------------------------------------------------------------
// Kernel B: cross-chunk scan, per (i,j) element, in place.
//   On exit g_S[b][c] holds the state ENTERING chunk c (h_in).
// ---------------------------------------------------------------------------
__global__ __launch_bounds__(256) void dr_scan_kernel()
{
    const int b = blockIdx.y;
    const int e = blockIdx.x * 256 + threadIdx.x;   // 0..65535
    __shared__ float gam[NCHUNK];
    if (threadIdx.x < NCHUNK) gam[threadIdx.x] = g_Gamma[b * NCHUNK + threadIdx.x];
    __syncthreads();

    float h = 0.f;
    const size_t base = (size_t)b * NCHUNK * DD * DD + e;
    #pragma unroll 4
    for (int c = 0; c < NCHUNK; c++) {
        const size_t off = base + (size_t)c * DD * DD;
        float s = g_S[off];
        g_S[off] = h;
        h = gam[c] * h + s;
    }
}

// ---------------------------------------------------------------------------
// Kernel C: per-chunk output
//   A[i][tau] = (tau<=i) ? exp(Lg[i]-Lg[tau]) * (q_i . k_tau) : 0
//   O[i][:]   = exp(Lg[i]) * (q_i @ Hin) + A[i][:] @ V
// One CTA per (b,c); 256 threads; output tile [64 x 256].
// ---------------------------------------------------------------------------
#define SD 260   // padded row stride (floats), 16B-aligned

__global__ __launch_bounds__(256) void dr_out_kernel(
    const float* __restrict__ Q,
    const float* __restrict__ K,
    const float* __restrict__ V,
    float* __restrict__ O)
{
    extern __shared__ float sm[];
    const int bc = blockIdx.x;
    const int b  = bc >> 6;
    const int c  = bc & 63;
    const int tid = threadIdx.x;

    float* Qs  = sm;                    // [64][SD]
    float* KH  = Qs + 64 * SD;          // [64][SD] as K rows; reused as H panel [64][256]
    float* Vs  = KH + 64 * SD;          // [64][SD]
    float* As  = Vs + 64 * SD;          // [64][65]
    float* sLg = As + 64 * 65;          // [64]
    float* sg  = sLg + 64;              // [64]

    if (tid < CC) {
        float lg = g_Lg[bc * CC + tid];
        sLg[tid] = lg;
        sg[tid]  = __expf(lg);
    }
    {
        const size_t rowbase = (size_t)b * SS + (size_t)c * CC;
        #pragma unroll
        for (int it = 0; it < 16; it++) {
            int idx = it * 1024 + tid * 4;    // 0..16383
            int row = idx >> 8, d = idx & 255;
            const size_t g = (rowbase + row) * DD + d;
            *(float4*)&Qs[row * SD + d] = *(const float4*)&Q[g];
            *(float4*)&KH[row * SD + d] = *(const float4*)&K[g];
            *(float4*)&Vs[row * SD + d] = *(const float4*)&V[g];
        }
    }
    __syncthreads();

    const int rt = tid >> 4;    // 0..15
    const int ct = tid & 15;    // 0..15
    const int i0 = rt * 4;

    // ---- Phase A: masked decayed attention matrix into As ----
    {
        float accA[4][4];
        #pragma unroll
        for (int r = 0; r < 4; r++)
            #pragma unroll
            for (int s2 = 0; s2 < 4; s2++) accA[r][s2] = 0.f;

        for (int d0 = 0; d0 < DD; d0 += 4) {
            float4 qv[4], kv[4];
            #pragma unroll
            for (int r = 0; r < 4; r++)  qv[r]  = *(float4*)&Qs[(i0 + r) * SD + d0];
            #pragma unroll
            for (int s2 = 0; s2 < 4; s2++) kv[s2] = *(float4*)&KH[(ct + 16 * s2) * SD + d0];
            #pragma unroll
            for (int r = 0; r < 4; r++)
                #pragma unroll
                for (int s2 = 0; s2 < 4; s2++) {
                    accA[r][s2] += qv[r].x * kv[s2].x;
                    accA[r][s2] += qv[r].y * kv[s2].y;
                    accA[r][s2] += qv[r].z * kv[s2].z;
                    accA[r][s2] += qv[r].w * kv[s2].w;
                }
        }
        #pragma unroll
        for (int r = 0; r < 4; r++)
            #pragma unroll
            for (int s2 = 0; s2 < 4; s2++) {
                const int i = i0 + r, tau = ct + 16 * s2;
                As[i * 65 + tau] =
                    (tau <= i) ? accA[r][s2] * __expf(sLg[i] - sLg[tau]) : 0.f;
            }
    }
    __syncthreads();   // As published; K region free for reuse

    float acc[4][16];
    #pragma unroll
    for (int r = 0; r < 4; r++)
        #pragma unroll
        for (int m = 0; m < 16; m++) acc[r][m] = 0.f;

    // ---- Phase QH: acc += Q @ Hin, panels of 64 rows of H ----
    const float* Hg = g_S + (size_t)bc * DD * DD;
    for (int p = 0; p < 4; p++) {
        if (p) __syncthreads();
        #pragma unroll
        for (int it = 0; it < 16; it++) {
            int idx = it * 1024 + tid * 4;
            int row = idx >> 8, d = idx & 255;
            *(float4*)&KH[row * 256 + d] =
                *(const float4*)&Hg[(size_t)(p * 64 + row) * DD + d];
        }
        __syncthreads();
        for (int d = 0; d < 64; d++) {
            float qv[4];
            #pragma unroll
            for (int r = 0; r < 4; r++) qv[r] = Qs[(i0 + r) * SD + p * 64 + d];
            #pragma unroll
            for (int m = 0; m < 16; m++) {
                const float hv = KH[d * 256 + ct + 16 * m];
                #pragma unroll
                for (int r = 0; r < 4; r++) acc[r][m] += qv[r] * hv;
            }
        }
    }

    // ---- scale by g_i ----
    #pragma unroll
    for (int r = 0; r < 4; r++) {
        const float gi = sg[i0 + r];
        #pragma unroll
        for (int m = 0; m < 16; m++) acc[r][m] *= gi;
    }

    // ---- Phase AV: acc += A @ V ----
    for (int tau = 0; tau < CC; tau++) {
        float av[4];
        #pragma unroll
        for (int r = 0; r < 4; r++) av[r] = As[(i0 + r) * 65 + tau];
        #pragma unroll
        for (int m = 0; m < 16; m++) {
            const float vv = Vs[tau * SD + ct + 16 * m];
            #pragma unroll
            for (int r = 0; r < 4; r++) acc[r][m] += av[r] * vv;
        }
    }

    // ---- store ----
    #pragma unroll
    for (int r = 0; r < 4; r++) {
        const size_t row = ((size_t)b * SS + (size_t)c * CC + i0 + r) * DD;
        #pragma unroll
        for (int m = 0; m < 16; m++)
            O[row + ct + 16 * m] = acc[r][m];
    }
}

// ---------------------------------------------------------------------------
extern "C" void kernel_launch(void* const* d_in, const int* in_sizes, int n_in,
                              void* d_out, int out_size)
{
    const float* q    = (const float*)d_in[0];
    const float* k    = (const float*)d_in[1];
    const float* v    = (const float*)d_in[2];
    const float* beta = (const float*)d_in[3];
    float* out = (float*)d_out;

    (void)in_sizes; (void)n_in; (void)out_size;

    // Kernel A: 512 (b,c) x 4 quadrants
    dr_state_kernel<<<dim3(BB * NCHUNK, 4), 256>>>(k, v, beta);

    // Kernel B: elementwise cross-chunk scan (in place)
    dr_scan_kernel<<<dim3(DD * DD / 256, BB), 256>>>();

    // Kernel C: outputs, 211 KB dynamic smem
    const int smemC = (3 * 64 * SD + 64 * 65 + 128) * (int)sizeof(float);
    cudaFuncSetAttribute(dr_out_kernel,
                         cudaFuncAttributeMaxDynamicSharedMemorySize, smemC);
    dr_out_kernel<<<BB * NCHUNK, 256, smemC>>>(q, k, v, out);
}

// round 3
// speedup vs baseline: 2.5697x; 2.5697x over previous
#include <cuda_runtime.h>
#include <cuda_bf16.h>
#include <cstdint>
#include <cstddef>

#define BB 8
#define SS 4096
#define DD 256
#define CC 64
#define NCHUNK 64
#define NBC (BB * NCHUNK)   // 512

// Scratch
__device__ float         g_S [(size_t)NBC * DD * DD];   // per-chunk S, [bc][i][j] (134 MB)
__device__ __nv_bfloat16 g_Hh[(size_t)NBC * DD * DD];   // incoming state hi (67 MB)
__device__ __nv_bfloat16 g_Hl[(size_t)NBC * DD * DD];   // incoming state lo (67 MB)
__device__ float g_Lg[NBC * CC];
__device__ float g_Gamma[NBC];

// ---------------------------------------------------------------------------
// MMA / ldmatrix helpers (base-ISA only: valid on compute_103)
// ---------------------------------------------------------------------------
__device__ __forceinline__ uint32_t smem_u32(const void* p) {
    uint32_t a;
    asm("{ .reg .u64 t; cvta.to.shared.u64 t, %1; cvt.u32.u64 %0, t; }"
        : "=r"(a) : "l"(p));
    return a;
}

__device__ __forceinline__ void mma16816(float c[4], const uint32_t a[4],
                                         const uint32_t b[2]) {
    asm volatile(
        "mma.sync.aligned.m16n8k16.row.col.f32.bf16.bf16.f32 "
        "{%0,%1,%2,%3}, {%4,%5,%6,%7}, {%8,%9}, {%0,%1,%2,%3};"
        : "+f"(c[0]), "+f"(c[1]), "+f"(c[2]), "+f"(c[3])
        : "r"(a[0]), "r"(a[1]), "r"(a[2]), "r"(a[3]), "r"(b[0]), "r"(b[1]));
}

__device__ __forceinline__ void ldmx4(uint32_t r[4], uint32_t a) {
    asm volatile("ldmatrix.sync.aligned.m8n8.x4.shared.b16 {%0,%1,%2,%3}, [%4];"
                 : "=r"(r[0]), "=r"(r[1]), "=r"(r[2]), "=r"(r[3]) : "r"(a));
}
__device__ __forceinline__ void ldmx4t(uint32_t r[4], uint32_t a) {
    asm volatile("ldmatrix.sync.aligned.m8n8.x4.trans.shared.b16 {%0,%1,%2,%3}, [%4];"
                 : "=r"(r[0]), "=r"(r[1]), "=r"(r[2]), "=r"(r[3]) : "r"(a));
}
__device__ __forceinline__ void ldmx2(uint32_t r[2], uint32_t a) {
    asm volatile("ldmatrix.sync.aligned.m8n8.x2.shared.b16 {%0,%1}, [%2];"
                 : "=r"(r[0]), "=r"(r[1]) : "r"(a));
}

// Split fp32x4 -> bf16 hi/lo packed pairs.
__device__ __forceinline__ void split4(float4 v, uint2& hi, uint2& lo) {
    float x[4] = { v.x, v.y, v.z, v.w };
    uint32_t h[4], l[4];
    #pragma unroll
    for (int u = 0; u < 4; u++) {
        __nv_bfloat16 hb = __float2bfloat16(x[u]);
        float rres = x[u] - __bfloat162float(hb);
        __nv_bfloat16 lb = __float2bfloat16(rres);
        h[u] = (uint32_t)__bfloat16_as_ushort(hb);
        l[u] = (uint32_t)__bfloat16_as_ushort(lb);
    }
    hi.x = h[0] | (h[1] << 16); hi.y = h[2] | (h[3] << 16);
    lo.x = l[0] | (l[1] << 16); lo.y = l[2] | (l[3] << 16);
}

__device__ __forceinline__ uint32_t pack_bf16x2(float x, float y) {
    __nv_bfloat16 a = __float2bfloat16(x), b = __float2bfloat16(y);
    return (uint32_t)__bfloat16_as_ushort(a) |
           ((uint32_t)__bfloat16_as_ushort(b) << 16);
}

// smem strides (bf16 elements); all ≡ 8 (mod 16) so rows land 4 words apart mod 32
#define SK 264   // [*][256] tiles
#define SV 136   // [*][128] tiles
#define SAS 72   // [64][64] attention tile

// ---------------------------------------------------------------------------
// Kernel A: S[i][j] = sum_tau (w_tau K[tau][i]) V[tau][j], per (bc, jh-half).
// ---------------------------------------------------------------------------
#define A_WV   0
#define A_LG   256
#define A_KH   512
#define A_KL   (A_KH + 64 * SK * 2)      // +33792
#define A_VH   (A_KL + 64 * SK * 2)
#define A_VL   (A_VH + 64 * SV * 2)      // +17408
#define A_SMEM (A_VL + 64 * SV * 2)      // 102912

__global__ __launch_bounds__(256) void dr_state(
    const float* __restrict__ K, const float* __restrict__ V,
    const float* __restrict__ beta)
{
    extern __shared__ char sm[];
    float* wv  = (float*)(sm + A_WV);
    float* sLg = (float*)(sm + A_LG);
    const int bc = blockIdx.x, jh = blockIdx.y;
    const int b = bc >> 6, c = bc & 63;
    const int tid = threadIdx.x, wid = tid >> 5, lane = tid & 31;

    if (tid < CC) sLg[tid] = __logf(fmaxf(beta[b * SS + c * CC + tid], 1e-30f));
    __syncthreads();
    if (tid == 0) {
        float s = 0.f;
        #pragma unroll
        for (int u = 0; u < CC; u++) { s += sLg[u]; sLg[u] = s; }
    }
    __syncthreads();
    const float LgEnd = sLg[CC - 1];
    if (tid < CC) {
        wv[tid] = __expf(LgEnd - sLg[tid]);
        if (jh == 0) g_Lg[bc * CC + tid] = sLg[tid];
    }
    if (jh == 0 && tid == 0) g_Gamma[bc] = __expf(LgEnd);
    __syncthreads();

    __nv_bfloat16* KH = (__nv_bfloat16*)(sm + A_KH);
    __nv_bfloat16* KL = (__nv_bfloat16*)(sm + A_KL);
    __nv_bfloat16* VH = (__nv_bfloat16*)(sm + A_VH);
    __nv_bfloat16* VL = (__nv_bfloat16*)(sm + A_VL);

    const float* Kg = K + ((size_t)b * SS + (size_t)c * CC) * DD;
    const float* Vg = V + ((size_t)b * SS + (size_t)c * CC) * DD + jh * 128;

    #pragma unroll
    for (int it = 0; it < 16; it++) {                 // K*w -> [tau][i] hi/lo
        int idx = it * 256 + tid;
        int tau = idx >> 6, c4 = (idx & 63) << 2;
        float4 kq = *(const float4*)(Kg + (size_t)tau * DD + c4);
        float wt = wv[tau];
        float4 sc = { kq.x * wt, kq.y * wt, kq.z * wt, kq.w * wt };
        uint2 h, l; split4(sc, h, l);
        *(uint2*)(KH + tau * SK + c4) = h;
        *(uint2*)(KL + tau * SK + c4) = l;
    }
    #pragma unroll
    for (int it = 0; it < 8; it++) {                  // V half -> [tau][j] hi/lo
        int idx = it * 256 + tid;
        int tau = idx >> 5, c4 = (idx & 31) << 2;
        float4 vq = *(const float4*)(Vg + (size_t)tau * DD + c4);
        uint2 h, l; split4(vq, h, l);
        *(uint2*)(VH + tau * SV + c4) = h;
        *(uint2*)(VL + tau * SV + c4) = l;
    }
    __syncthreads();

    const int mat = lane >> 3, r = lane & 7, g = lane >> 2, q = lane & 3;
    // trans-A (stored [k][m], stride SK): row = k0+(mat>>1)*8+r, col = m0+(mat&1)*8
    const uint32_t offA = (uint32_t)((((mat >> 1) * 8 + r) * (SK * 2)) + (mat & 1) * 16);
    // trans-B (stored [k][n], stride SV): row = k0+(mat&1)*8+r, col = n0+(mat>>1)*8
    const uint32_t offB = (uint32_t)((((mat & 1) * 8 + r) * (SV * 2)) + (mat >> 1) * 16);
    const uint32_t khb = smem_u32(sm + A_KH), klb = smem_u32(sm + A_KL);
    const uint32_t vhb = smem_u32(sm + A_VH), vlb = smem_u32(sm + A_VL);

    const int wm = wid >> 1, wn = wid & 1;
    const int i0w = wm * 64, j0w = wn * 64;

    float acc[4][8][4];
    #pragma unroll
    for (int mt = 0; mt < 4; mt++)
        #pragma unroll
        for (int nt = 0; nt < 8; nt++)
            #pragma unroll
            for (int u = 0; u < 4; u++) acc[mt][nt][u] = 0.f;

    #pragma unroll
    for (int pass = 0; pass < 3; pass++) {
        uint32_t ab = (pass == 2) ? klb : khb;
        uint32_t bb = (pass == 1) ? vlb : vhb;
        #pragma unroll
        for (int k0 = 0; k0 < 64; k0 += 16) {
            uint32_t af[4][4], bfm[4][4];
            #pragma unroll
            for (int mt = 0; mt < 4; mt++)
                ldmx4t(af[mt], ab + (uint32_t)(k0 * (SK * 2) + (i0w + mt * 16) * 2) + offA);
            #pragma unroll
            for (int ng = 0; ng < 4; ng++)
                ldmx4t(bfm[ng], bb + (uint32_t)(k0 * (SV * 2) + (j0w + ng * 16) * 2) + offB);
            #pragma unroll
            for (int mt = 0; mt < 4; mt++)
                #pragma unroll
                for (int nt = 0; nt < 8; nt++)
                    mma16816(acc[mt][nt], af[mt], &bfm[nt >> 1][(nt & 1) * 2]);
        }
    }

    float* Sdst = g_S + (size_t)bc * 65536 + jh * 128;
    #pragma unroll
    for (int mt = 0; mt < 4; mt++)
        #pragma unroll
        for (int nt = 0; nt < 8; nt++) {
            int i = i0w + mt * 16 + g;
            int j = j0w + nt * 8 + 2 * q;
            float2 v0 = { acc[mt][nt][0], acc[mt][nt][1] };
            float2 v1 = { acc[mt][nt][2], acc[mt][nt][3] };
            *(float2*)(Sdst + (size_t)i * 256 + j) = v0;
            *(float2*)(Sdst + (size_t)(i + 8) * 256 + j) = v1;
        }
}

// ---------------------------------------------------------------------------
// Kernel B: cross-chunk scan (2 elems/thread); writes H (incoming state) bf16.
// ---------------------------------------------------------------------------
__global__ __launch_bounds__(256) void dr_scan()
{
    const int b = blockIdx.y;
    const int tid = threadIdx.x;
    const size_t e2 = ((size_t)blockIdx.x * 256 + tid) * 2;
    __shared__ float gam[NCHUNK];
    if (tid < NCHUNK) gam[tid] = g_Gamma[b * NCHUNK + tid];
    __syncthreads();

    float2 h = { 0.f, 0.f };
    const size_t base = (size_t)b * NCHUNK * 65536 + e2;
    for (int c = 0; c < NCHUNK; c++) {
        const size_t off = base + (size_t)c * 65536;
        float2 s = *(const float2*)(g_S + off);
        __nv_bfloat16 hx = __float2bfloat16(h.x), hy = __float2bfloat16(h.y);
        *(uint32_t*)(g_Hh + off) =
            (uint32_t)__bfloat16_as_ushort(hx) | ((uint32_t)__bfloat16_as_ushort(hy) << 16);
        *(uint32_t*)(g_Hl + off) =
            pack_bf16x2(h.x - __bfloat162float(hx), h.y - __bfloat162float(hy));
        float gc = gam[c];
        h.x = gc * h.x + s.x;
        h.y = gc * h.y + s.y;
    }
}

// ---------------------------------------------------------------------------
// Kernel C1: inter-chunk output O[i][j] = g_i * sum_d Q[i][d] H[d][j]
// ---------------------------------------------------------------------------
#define C_SG   0
#define C_QH   256
#define C_QL   (C_QH + 64 * SK * 2)
#define C_HH   (C_QL + 64 * SK * 2)
#define C_HL   (C_HH + 256 * SV * 2)     // +69632
#define C_SMEM (C_HL + 256 * SV * 2)     // 207104

__global__ __launch_bounds__(256) void dr_inter(
    const float* __restrict__ Q, float* __restrict__ O)
{
    extern __shared__ char sm[];
    float* sg = (float*)(sm + C_SG);
    const int bc = blockIdx.x, jh = blockIdx.y;
    const int b = bc >> 6, c = bc & 63;
    const int tid = threadIdx.x, wid = tid >> 5, lane = tid & 31;

    if (tid < 64) sg[tid] = __expf(g_Lg[bc * CC + tid]);

    __nv_bfloat16* QH = (__nv_bfloat16*)(sm + C_QH);
    __nv_bfloat16* QL = (__nv_bfloat16*)(sm + C_QL);
    __nv_bfloat16* HH = (__nv_bfloat16*)(sm + C_HH);
    __nv_bfloat16* HL = (__nv_bfloat16*)(sm + C_HL);

    const float* Qg = Q + ((size_t)b * SS + (size_t)c * CC) * DD;
    #pragma unroll
    for (int it = 0; it < 16; it++) {
        int idx = it * 256 + tid;
        int row = idx >> 6, c4 = (idx & 63) << 2;
        float4 qv = *(const float4*)(Qg + (size_t)row * DD + c4);
        uint2 h, l; split4(qv, h, l);
        *(uint2*)(QH + row * SK + c4) = h;
        *(uint2*)(QL + row * SK + c4) = l;
    }
    const __nv_bfloat16* HgH = g_Hh + (size_t)bc * 65536 + jh * 128;
    const __nv_bfloat16* HgL = g_Hl + (size_t)bc * 65536 + jh * 128;
    #pragma unroll
    for (int it = 0; it < 16; it++) {
        int idx = it * 256 + tid;
        int row = idx >> 4, u = (idx & 15) * 8;
        *(uint4*)(HH + row * SV + u) = *(const uint4*)(HgH + (size_t)row * 256 + u);
        *(uint4*)(HL + row * SV + u) = *(const uint4*)(HgL + (size_t)row * 256 + u);
    }
    __syncthreads();

    const int mat = lane >> 3, r = lane & 7, g = lane >> 2, q = lane & 3;
    const uint32_t offA = (uint32_t)((((mat & 1) * 8 + r) * (SK * 2)) + (mat >> 1) * 16); // non-trans A
    const uint32_t offB = (uint32_t)((((mat & 1) * 8 + r) * (SV * 2)) + (mat >> 1) * 16); // trans B
    const uint32_t qhb = smem_u32(sm + C_QH), qlb = smem_u32(sm + C_QL);
    const uint32_t hhb = smem_u32(sm + C_HH), hlb = smem_u32(sm + C_HL);

    const int wm = wid >> 2, wn = wid & 3;
    const int i0w = wm * 32, j0w = wn * 32;

    float acc[2][4][4];
    #pragma unroll
    for (int mt = 0; mt < 2; mt++)
        #pragma unroll
        for (int nt = 0; nt < 4; nt++)
            #pragma unroll
            for (int u = 0; u < 4; u++) acc[mt][nt][u] = 0.f;

    #pragma unroll
    for (int pass = 0; pass < 3; pass++) {
        uint32_t ab = (pass == 2) ? qlb : qhb;
        uint32_t bb = (pass == 1) ? hlb : hhb;
        for (int d0 = 0; d0 < 256; d0 += 16) {
            uint32_t af[2][4], bfm[2][4];
            #pragma unroll
            for (int mt = 0; mt < 2; mt++)
                ldmx4(af[mt], ab + (uint32_t)((i0w + mt * 16) * (SK * 2) + d0 * 2) + offA);
            #pragma unroll
            for (int ng = 0; ng < 2; ng++)
                ldmx4t(bfm[ng], bb + (uint32_t)(d0 * (SV * 2) + (j0w + ng * 16) * 2) + offB);
            #pragma unroll
            for (int mt = 0; mt < 2; mt++)
                #pragma unroll
                for (int nt = 0; nt < 4; nt++)
                    mma16816(acc[mt][nt], af[mt], &bfm[nt >> 1][(nt & 1) * 2]);
        }
    }

    float* Od = O + ((size_t)b * SS + (size_t)c * CC) * DD + jh * 128;
    #pragma unroll
    for (int mt = 0; mt < 2; mt++)
        #pragma unroll
        for (int nt = 0; nt < 4; nt++) {
            int i = i0w + mt * 16 + g;
            int j = j0w + nt * 8 + 2 * q;
            float s0 = sg[i], s1 = sg[i + 8];
            float2 v0 = { acc[mt][nt][0] * s0, acc[mt][nt][1] * s0 };
            float2 v1 = { acc[mt][nt][2] * s1, acc[mt][nt][3] * s1 };
            *(float2*)(Od + (size_t)i * DD + j) = v0;
            *(float2*)(Od + (size_t)(i + 8) * DD + j) = v1;
        }
}

// ---------------------------------------------------------------------------
// Kernel C2: intra-chunk attention via tensor cores; O += A_att @ V.
// ---------------------------------------------------------------------------
#define I_LG   0
#define I_QVH  256
#define I_QVL  (I_QVH + 64 * SK * 2)
#define I_KH2  (I_QVL + 64 * SK * 2)
#define I_KL2  (I_KH2 + 64 * SK * 2)
#define I_ASH  (I_KL2 + 64 * SK * 2)
#define I_ASL  (I_ASH + 64 * SAS * 2)    // +9216
#define I_SMEM (I_ASL + 64 * SAS * 2)    // 153856

__global__ __launch_bounds__(256) void dr_intra(
    const float* __restrict__ Q, const float* __restrict__ K,
    const float* __restrict__ V, float* __restrict__ O)
{
    extern __shared__ char sm[];
    float* sLg = (float*)(sm + I_LG);
    const int bc = blockIdx.x;
    const int b = bc >> 6, c = bc & 63;
    const int tid = threadIdx.x, wid = tid >> 5, lane = tid & 31;

    if (tid < 64) sLg[tid] = g_Lg[bc * CC + tid];

    __nv_bfloat16* QVH = (__nv_bfloat16*)(sm + I_QVH);
    __nv_bfloat16* QVL = (__nv_bfloat16*)(sm + I_QVL);
    __nv_bfloat16* KH2 = (__nv_bfloat16*)(sm + I_KH2);
    __nv_bfloat16* KL2 = (__nv_bfloat16*)(sm + I_KL2);

    const size_t chbase = ((size_t)b * SS + (size_t)c * CC) * DD;
    #pragma unroll
    for (int it = 0; it < 16; it++) {
        int idx = it * 256 + tid;
        int row = idx >> 6, c4 = (idx & 63) << 2;
        float4 qv = *(const float4*)(Q + chbase + (size_t)row * DD + c4);
        uint2 h, l; split4(qv, h, l);
        *(uint2*)(QVH + row * SK + c4) = h;
        *(uint2*)(QVL + row * SK + c4) = l;
        float4 kv = *(const float4*)(K + chbase + (size_t)row * DD + c4);
        split4(kv, h, l);
        *(uint2*)(KH2 + row * SK + c4) = h;
        *(uint2*)(KL2 + row * SK + c4) = l;
    }
    __syncthreads();

    const int mat = lane >> 3, r = lane & 7, g = lane >> 2, q = lane & 3;
    const int ln = lane & 15;
    const uint32_t offA  = (uint32_t)((((mat & 1) * 8 + r) * (SK * 2)) + (mat >> 1) * 16); // non-trans A, SK
    const uint32_t offB2 = (uint32_t)((ln & 7) * (SK * 2) + (ln >> 3) * 16);               // non-trans B x2, SK
    const uint32_t qvh = smem_u32(sm + I_QVH), qvl = smem_u32(sm + I_QVL);
    const uint32_t kh2 = smem_u32(sm + I_KH2), kl2 = smem_u32(sm + I_KL2);

    // Phase 1: QK^T -> 64x64
    const int wm1 = wid >> 2, wn1 = wid & 3;
    const int i0 = wm1 * 32, t0 = wn1 * 16;
    float acc1[2][2][4];
    #pragma unroll
    for (int mt = 0; mt < 2; mt++)
        #pragma unroll
        for (int nt = 0; nt < 2; nt++)
            #pragma unroll
            for (int u = 0; u < 4; u++) acc1[mt][nt][u] = 0.f;

    #pragma unroll
    for (int pass = 0; pass < 3; pass++) {
        uint32_t ab = (pass == 2) ? qvl : qvh;
        uint32_t bb = (pass == 1) ? kl2 : kh2;
        for (int d0 = 0; d0 < 256; d0 += 16) {
            uint32_t af[2][4], bfr[2][2];
            #pragma unroll
            for (int mt = 0; mt < 2; mt++)
                ldmx4(af[mt], ab + (uint32_t)((i0 + mt * 16) * (SK * 2) + d0 * 2) + offA);
            #pragma unroll
            for (int nt = 0; nt < 2; nt++)
                ldmx2(bfr[nt], bb + (uint32_t)((t0 + nt * 8) * (SK * 2) + d0 * 2) + offB2);
            #pragma unroll
            for (int mt = 0; mt < 2; mt++)
                #pragma unroll
                for (int nt = 0; nt < 2; nt++)
                    mma16816(acc1[mt][nt], af[mt], bfr[nt]);
        }
    }

    // Mask + decay -> As (bf16 hi/lo, [i][tau] stride SAS)
    __nv_bfloat16* ASH = (__nv_bfloat16*)(sm + I_ASH);
    __nv_bfloat16* ASL = (__nv_bfloat16*)(sm + I_ASL);
    #pragma unroll
    for (int mt = 0; mt < 2; mt++)
        #pragma unroll
        for (int nt = 0; nt < 2; nt++) {
            int ia = i0 + mt * 16 + g, ib = ia + 8;
            int t = t0 + nt * 8 + 2 * q;
            float la = sLg[ia], lb = sLg[ib], l0 = sLg[t], l1 = sLg[t + 1];
            float f00 = (t     <= ia) ? __expf(la - l0) : 0.f;
            float f01 = (t + 1 <= ia) ? __expf(la - l1) : 0.f;
            float f10 = (t     <= ib) ? __expf(lb - l0) : 0.f;
            float f11 = (t + 1 <= ib) ? __expf(lb - l1) : 0.f;
            float a0 = acc1[mt][nt][0] * f00, a1 = acc1[mt][nt][1] * f01;
            float a2 = acc1[mt][nt][2] * f10, a3 = acc1[mt][nt][3] * f11;
            __nv_bfloat16 h0 = __float2bfloat16(a0), h1 = __float2bfloat16(a1);
            __nv_bfloat16 h2 = __float2bfloat16(a2), h3 = __float2bfloat16(a3);
            *(uint32_t*)(ASH + ia * SAS + t) =
                (uint32_t)__bfloat16_as_ushort(h0) | ((uint32_t)__bfloat16_as_ushort(h1) << 16);
            *(uint32_t*)(ASH + ib * SAS + t) =
                (uint32_t)__bfloat16_as_ushort(h2) | ((uint32_t)__bfloat16_as_ushort(h3) << 16);
            *(uint32_t*)(ASL + ia * SAS + t) =
                pack_bf16x2(a0 - __bfloat162float(h0), a1 - __bfloat162float(h1));
            *(uint32_t*)(ASL + ib * SAS + t) =
                pack_bf16x2(a2 - __bfloat162float(h2), a3 - __bfloat162float(h3));
        }
    __syncthreads();

    // Reload QV region with V
    #pragma unroll
    for (int it = 0; it < 16; it++) {
        int idx = it * 256 + tid;
        int row = idx >> 6, c4 = (idx & 63) << 2;
        float4 vv = *(const float4*)(V + chbase + (size_t)row * DD + c4);
        uint2 h, l; split4(vv, h, l);
        *(uint2*)(QVH + row * SK + c4) = h;
        *(uint2*)(QVL + row * SK + c4) = l;
    }
    __syncthreads();

    // Phase 2: O += As @ V
    const int wm2 = wid >> 2, wn2 = wid & 3;
    const int i0b = wm2 * 32, j0 = wn2 * 64;
    const uint32_t offAs = (uint32_t)((((mat & 1) * 8 + r) * (SAS * 2)) + (mat >> 1) * 16); // non-trans A, SAS
    const uint32_t offBv = (uint32_t)((((mat & 1) * 8 + r) * (SK * 2)) + (mat >> 1) * 16);  // trans B, SK
    const uint32_t ash = smem_u32(sm + I_ASH), asl = smem_u32(sm + I_ASL);

    float acc2[2][8][4];
    #pragma unroll
    for (int mt = 0; mt < 2; mt++)
        #pragma unroll
        for (int nt = 0; nt < 8; nt++)
            #pragma unroll
            for (int u = 0; u < 4; u++) acc2[mt][nt][u] = 0.f;

    #pragma unroll
    for (int pass = 0; pass < 3; pass++) {
        uint32_t ab = (pass == 2) ? asl : ash;
        uint32_t bb = (pass == 1) ? qvl : qvh;
        #pragma unroll
        for (int k0 = 0; k0 < 64; k0 += 16) {
            uint32_t af[2][4], bfm[4][4];
            #pragma unroll
            for (int mt = 0; mt < 2; mt++)
                ldmx4(af[mt], ab + (uint32_t)((i0b + mt * 16) * (SAS * 2) + k0 * 2) + offAs);
            #pragma unroll
            for (int ng = 0; ng < 4; ng++)
                ldmx4t(bfm[ng], bb + (uint32_t)(k0 * (SK * 2) + (j0 + ng * 16) * 2) + offBv);
            #pragma unroll
            for (int mt = 0; mt < 2; mt++)
                #pragma unroll
                for (int nt = 0; nt < 8; nt++)
                    mma16816(acc2[mt][nt], af[mt], &bfm[nt >> 1][(nt & 1) * 2]);
        }
    }

    float* Od = O + chbase;
    #pragma unroll
    for (int mt = 0; mt < 2; mt++)
        #pragma unroll
        for (int nt = 0; nt < 8; nt++) {
            int i = i0b + mt * 16 + g;
            int j = j0 + nt * 8 + 2 * q;
            float2* p0 = (float2*)(Od + (size_t)i * DD + j);
            float2 v0 = *p0;
            v0.x += acc2[mt][nt][0]; v0.y += acc2[mt][nt][1];
            *p0 = v0;
            float2* p1 = (float2*)(Od + (size_t)(i + 8) * DD + j);
            float2 v1 = *p1;
            v1.x += acc2[mt][nt][2]; v1.y += acc2[mt][nt][3];
            *p1 = v1;
        }
}

// ---------------------------------------------------------------------------
extern "C" void kernel_launch(void* const* d_in, const int* in_sizes, int n_in,
                              void* d_out, int out_size)
{
    const float* q    = (const float*)d_in[0];
    const float* k    = (const float*)d_in[1];
    const float* v    = (const float*)d_in[2];
    const float* beta = (const float*)d_in[3];
    float* out = (float*)d_out;
    (void)in_sizes; (void)n_in; (void)out_size;

    cudaFuncSetAttribute(dr_state, cudaFuncAttributeMaxDynamicSharedMemorySize, A_SMEM);
    cudaFuncSetAttribute(dr_inter, cudaFuncAttributeMaxDynamicSharedMemorySize, C_SMEM);
    cudaFuncSetAttribute(dr_intra, cudaFuncAttributeMaxDynamicSharedMemorySize, I_SMEM);

    dr_state<<<dim3(NBC, 2), 256, A_SMEM>>>(k, v, beta);
    dr_scan<<<dim3(128, BB), 256>>>();
    dr_inter<<<dim3(NBC, 2), 256, C_SMEM>>>(q, out);
    dr_intra<<<NBC, 256, I_SMEM>>>(q, k, v, out);
}